// round 2
// baseline (speedup 1.0000x reference)
#include <cuda_runtime.h>

// ---------------------------------------------------------------------------
// FFT long conv. Reference applies filter (b*D+d)//B = b*32 + (d>>3) to (b,d).
// Rows sharing a filter are same-b, adjacent-d groups of 8, so pack adjacent
// channel pairs (d, d+1) into one complex signal z = u[...,d] + i*u[...,d+1]:
//   w = IFFT( FFT(z) .* H_phi ),  Re(w)->d, Im(w)->d+1.
// Packed row index r = b*128 + (d>>1); filter phi = r >> 2.
// Forward DIF (natural->digit-reversed), pointwise mul in permuted order,
// inverse DIT (digit-reversed->natural). No reordering passes needed.
// ---------------------------------------------------------------------------

#define NFFT 16384
#define LSEQ 8192
#define KLEN 8192
#define DDIM 256
#define BATCH 8
#define CPAIR 128                 // DDIM/2 float2 channel-pairs
#define NROWS (BATCH * CPAIR)     // 1024
#define START ((KLEN - 1) / 2)    // 4095
#define NTHREADS 512

#define PHYS(i) ((i) + ((i) >> 4))
#define SMEM_F2 (NFFT + (NFFT >> 4))                  // 17408 float2
#define SMEM_BYTES (SMEM_F2 * (int)sizeof(float2))    // 139264 B

// scratch (static device allocations are the sanctioned workaround)
__device__ float2 g_Z[NROWS * LSEQ];   // packed input rows   (64 MB)
__device__ float2 g_W[NROWS * LSEQ];   // packed output rows  (64 MB)
__device__ float2 g_H[DDIM * NFFT];    // filter spectra, digit-reversed, pre-scaled 1/N (32 MB)

__device__ __forceinline__ float2 cmulf(float2 a, float2 b) {
    return make_float2(fmaf(a.x, b.x, -a.y * b.y), fmaf(a.x, b.y, a.y * b.x));
}

// DFT4 with omega = exp(DIR * 2*pi*i/4); DIR = -1 forward, +1 inverse
template<int DIR>
__device__ __forceinline__ void dft4(float2& a, float2& b, float2& c, float2& d) {
    float2 t0 = make_float2(a.x + c.x, a.y + c.y);
    float2 t1 = make_float2(a.x - c.x, a.y - c.y);
    float2 t2 = make_float2(b.x + d.x, b.y + d.y);
    float2 t3 = make_float2(b.x - d.x, b.y - d.y);
    a = make_float2(t0.x + t2.x, t0.y + t2.y);
    c = make_float2(t0.x - t2.x, t0.y - t2.y);
    if (DIR < 0) {
        b = make_float2(t1.x + t3.y, t1.y - t3.x);   // t1 - i*t3
        d = make_float2(t1.x - t3.y, t1.y + t3.x);   // t1 + i*t3
    } else {
        b = make_float2(t1.x - t3.y, t1.y + t3.x);
        d = make_float2(t1.x + t3.y, t1.y - t3.x);
    }
}

// multiply by (c + i*DIR*s), constants fold at compile time
template<int DIR>
__device__ __forceinline__ float2 twc(float2 a, float c, float s) {
    const float si = (DIR < 0) ? -s : s;
    return make_float2(a.x * c - a.y * si, a.x * si + a.y * c);
}

// In-register DFT16 (two radix-4 layers). Input: natural order v[m].
// Output: slot s = 4*(r&3) + (r>>2) holds spectral index r (digit-reversed).
template<int DIR>
__device__ __forceinline__ void dft16(float2 v[16]) {
    dft4<DIR>(v[0], v[4], v[8],  v[12]);
    dft4<DIR>(v[1], v[5], v[9],  v[13]);
    dft4<DIR>(v[2], v[6], v[10], v[14]);
    dft4<DIR>(v[3], v[7], v[11], v[15]);
    const float C1 = 0.9238795325112867f, S1 = 0.3826834323650898f;
    const float R2 = 0.7071067811865476f;
    v[5]  = twc<DIR>(v[5],  C1,  S1);                                  // W16^1
    v[9]  = twc<DIR>(v[9],  R2,  R2);                                  // W16^2
    v[13] = twc<DIR>(v[13], S1,  C1);                                  // W16^3
    v[6]  = twc<DIR>(v[6],  R2,  R2);                                  // W16^2
    v[10] = (DIR < 0) ? make_float2(v[10].y, -v[10].x)                 // * -i
                      : make_float2(-v[10].y, v[10].x);                // * +i
    v[14] = twc<DIR>(v[14], -R2,  R2);                                 // W16^6
    v[7]  = twc<DIR>(v[7],   S1,  C1);                                 // W16^3
    v[11] = twc<DIR>(v[11], -R2,  R2);                                 // W16^6
    v[15] = twc<DIR>(v[15], -C1, -S1);                                 // W16^9
    dft4<DIR>(v[0],  v[1],  v[2],  v[3]);
    dft4<DIR>(v[4],  v[5],  v[6],  v[7]);
    dft4<DIR>(v[8],  v[9],  v[10], v[11]);
    dft4<DIR>(v[12], v[13], v[14], v[15]);
}

// One radix-16 pass over smem. Forward (DIR=-1): DFT16 then post-twiddle W_M^{j r}.
// Inverse (DIR=+1): pre-twiddle conj then inverse DFT16. Each inverse pass is
// exactly 16 * (forward pass)^-1; the 1/N is folded into g_H.
template<int DIR, int M>
__device__ __forceinline__ void radix16_stage(float2* s, int tid) {
    constexpr int Ms = M >> 4;
    #pragma unroll
    for (int it = 0; it < (NFFT / 16) / NTHREADS; it++) {
        int g = tid + it * NTHREADS;
        int blk = (g / Ms) * M;
        int j   = g % Ms;
        int base = blk + j;
        float sv, cv;
        sincospif(2.0f * (float)j / (float)M, &sv, &cv);
        float2 w1 = make_float2(cv, (DIR < 0) ? -sv : sv);
        float2 v[16];
        if (DIR < 0) {
            #pragma unroll
            for (int m = 0; m < 16; m++) v[m] = s[PHYS(base + m * Ms)];
            dft16<DIR>(v);
            s[PHYS(base)] = v[0];
            float2 wr = w1;
            #pragma unroll
            for (int r = 1; r < 16; r++) {
                int sl = ((r & 3) << 2) | (r >> 2);
                s[PHYS(base + r * Ms)] = cmulf(v[sl], wr);
                wr = cmulf(wr, w1);
            }
        } else {
            v[0] = s[PHYS(base)];
            float2 wr = w1;
            #pragma unroll
            for (int r = 1; r < 16; r++) {
                v[r] = cmulf(s[PHYS(base + r * Ms)], wr);
                wr = cmulf(wr, w1);
            }
            dft16<DIR>(v);
            #pragma unroll
            for (int m = 0; m < 16; m++) {
                int sl = ((m & 3) << 2) | (m >> 2);
                s[PHYS(base + m * Ms)] = v[sl];
            }
        }
    }
    __syncthreads();
}

template<int DIR>
__device__ __forceinline__ void radix4_stage(float2* s, int tid) {
    #pragma unroll
    for (int it = 0; it < (NFFT / 4) / NTHREADS; it++) {
        int base = (tid + it * NTHREADS) * 4;
        float2 a = s[PHYS(base + 0)], b = s[PHYS(base + 1)];
        float2 c = s[PHYS(base + 2)], d = s[PHYS(base + 3)];
        dft4<DIR>(a, b, c, d);
        s[PHYS(base + 0)] = a; s[PHYS(base + 1)] = b;
        s[PHYS(base + 2)] = c; s[PHYS(base + 3)] = d;
    }
    __syncthreads();
}

__device__ __forceinline__ void fft_fwd(float2* s, int tid) {
    radix16_stage<-1, 16384>(s, tid);
    radix16_stage<-1, 1024>(s, tid);
    radix16_stage<-1, 64>(s, tid);
    radix4_stage<-1>(s, tid);
}

__device__ __forceinline__ void fft_inv(float2* s, int tid) {
    radix4_stage<1>(s, tid);
    radix16_stage<1, 64>(s, tid);
    radix16_stage<1, 1024>(s, tid);
    radix16_stage<1, 16384>(s, tid);
}

// ---------------------------------------------------------------------------
// Kernel 1: per-batch float2 transpose.  u viewed as (B, L, 128) float2.
// g_Z[(b*128 + c)][l] = u2[b, l, c]   (pair = channels 2c, 2c+1)
// ---------------------------------------------------------------------------
__global__ void __launch_bounds__(256) k_pack(const float* __restrict__ u) {
    __shared__ float2 tile[32][33];
    const int b  = blockIdx.z;
    const int c0 = blockIdx.y * 32;
    const int l0 = blockIdx.x * 32;
    const int tx = threadIdx.x, ty = threadIdx.y;
    const float2* __restrict__ u2 = (const float2*)u;
    #pragma unroll
    for (int i = 0; i < 4; i++) {
        int l = l0 + ty + 8 * i;
        tile[tx][ty + 8 * i] = u2[((size_t)b * LSEQ + l) * CPAIR + (c0 + tx)];
    }
    __syncthreads();
    #pragma unroll
    for (int i = 0; i < 4; i++) {
        int c = c0 + ty + 8 * i;
        int l = l0 + tx;
        g_Z[((size_t)b * CPAIR + c) * LSEQ + l] = tile[ty + 8 * i][tx];
    }
}

// ---------------------------------------------------------------------------
// Kernel 2: per-filter forward FFT of h, stored digit-reversed, pre-scaled 1/N
// ---------------------------------------------------------------------------
__global__ void __launch_bounds__(NTHREADS, 1) k_hfft(const float* __restrict__ h) {
    extern __shared__ float2 s[];
    const int d = blockIdx.x, tid = threadIdx.x;
    for (int i = tid; i < KLEN; i += NTHREADS)
        s[PHYS(i)] = make_float2(h[(size_t)d * KLEN + i], 0.f);
    for (int i = KLEN + tid; i < NFFT; i += NTHREADS)
        s[PHYS(i)] = make_float2(0.f, 0.f);
    __syncthreads();
    fft_fwd(s, tid);
    const float inv = 1.0f / (float)NFFT;
    for (int i = tid; i < NFFT; i += NTHREADS) {
        float2 v = s[PHYS(i)];
        g_H[(size_t)d * NFFT + i] = make_float2(v.x * inv, v.y * inv);
    }
}

// ---------------------------------------------------------------------------
// Kernel 3: per packed row: FFT -> .*H -> IFFT -> keep [START, START+L)
// Filter index phi = row >> 2  (row = b*128 + c, phi = b*32 + (c>>2))
// ---------------------------------------------------------------------------
__global__ void __launch_bounds__(NTHREADS, 1) k_conv() {
    extern __shared__ float2 s[];
    const int row = blockIdx.x;          // 0..1023
    const int phi = row >> 2;
    const int tid = threadIdx.x;
    const float2* __restrict__ zr = g_Z + (size_t)row * LSEQ;
    for (int i = tid; i < LSEQ; i += NTHREADS) s[PHYS(i)] = zr[i];
    for (int i = LSEQ + tid; i < NFFT; i += NTHREADS) s[PHYS(i)] = make_float2(0.f, 0.f);
    __syncthreads();
    fft_fwd(s, tid);
    const float2* __restrict__ Hd = g_H + (size_t)phi * NFFT;
    for (int i = tid; i < NFFT; i += NTHREADS)
        s[PHYS(i)] = cmulf(s[PHYS(i)], Hd[i]);
    __syncthreads();
    fft_inv(s, tid);
    float2* __restrict__ wr = g_W + (size_t)row * LSEQ;
    for (int l = tid; l < LSEQ; l += NTHREADS)
        wr[l] = s[PHYS(START + l)];
}

// ---------------------------------------------------------------------------
// Kernel 4: per-batch float2 transpose back.  y2[b, l, c] = g_W[b*128+c][l]
// ---------------------------------------------------------------------------
__global__ void __launch_bounds__(256) k_unpack(float* __restrict__ y) {
    __shared__ float2 tile[32][33];
    const int b  = blockIdx.z;
    const int c0 = blockIdx.y * 32;
    const int l0 = blockIdx.x * 32;
    const int tx = threadIdx.x, ty = threadIdx.y;
    float2* __restrict__ y2 = (float2*)y;
    #pragma unroll
    for (int i = 0; i < 4; i++) {
        int c = c0 + ty + 8 * i;
        int l = l0 + tx;
        tile[ty + 8 * i][tx] = g_W[((size_t)b * CPAIR + c) * LSEQ + l];
    }
    __syncthreads();
    #pragma unroll
    for (int i = 0; i < 4; i++) {
        int l = l0 + ty + 8 * i;
        y2[((size_t)b * LSEQ + l) * CPAIR + (c0 + tx)] = tile[tx][ty + 8 * i];
    }
}

// ---------------------------------------------------------------------------
extern "C" void kernel_launch(void* const* d_in, const int* in_sizes, int n_in,
                              void* d_out, int out_size) {
    (void)in_sizes; (void)n_in; (void)out_size;
    const float* u = (const float*)d_in[0];
    const float* h = (const float*)d_in[1];
    float* y = (float*)d_out;

    cudaFuncSetAttribute(k_hfft, cudaFuncAttributeMaxDynamicSharedMemorySize, SMEM_BYTES);
    cudaFuncSetAttribute(k_conv, cudaFuncAttributeMaxDynamicSharedMemorySize, SMEM_BYTES);

    dim3 tb(32, 8);
    dim3 tg(LSEQ / 32, CPAIR / 32, BATCH);

    k_pack<<<tg, tb>>>(u);
    k_hfft<<<DDIM, NTHREADS, SMEM_BYTES>>>(h);
    k_conv<<<NROWS, NTHREADS, SMEM_BYTES>>>();
    k_unpack<<<tg, tb>>>(y);
}

// round 3
// speedup vs baseline: 1.4903x; 1.4903x over previous
#include <cuda_runtime.h>

// ---------------------------------------------------------------------------
// FFT long conv. Filter for (b,d) is b*32 + (d>>3); pack adjacent channel
// pairs (d,d+1) as z = u[...,d] + i*u[...,d+1] (contiguous float2 in u!).
//   w = IFFT( FFT(z) .* H_phi ),  Re->d, Im->d+1.  row r = b*128+(d>>1), phi=r>>2.
// Forward DIF (natural->digit-reversed), mul in permuted order, inverse DIT.
// Fusions: stage1 loads global directly (half-zero DFT16); fwd-r4/mul/inv-r4
// fused in registers; last inverse stage writes window directly to global.
// ---------------------------------------------------------------------------

#define NFFT 16384
#define LSEQ 8192
#define KLEN 8192
#define DDIM 256
#define BATCH 8
#define CPAIR 128
#define NROWS (BATCH * CPAIR)     // 1024
#define START ((KLEN - 1) / 2)    // 4095
#define NTHREADS 512

#define PHYS(i) ((i) + ((i) >> 4))
#define SMEM_F2 (NFFT + (NFFT >> 4))
#define SMEM_BYTES (SMEM_F2 * (int)sizeof(float2))    // 139264 B

__device__ float2 g_Z[NROWS * LSEQ];   // packed input rows   (64 MB)
__device__ float2 g_W[NROWS * LSEQ];   // packed output rows  (64 MB)
__device__ float2 g_H[DDIM * NFFT];    // filter spectra, digit-reversed, /N  (32 MB)

__device__ __forceinline__ float2 cmulf(float2 a, float2 b) {
    return make_float2(fmaf(a.x, b.x, -a.y * b.y), fmaf(a.x, b.y, a.y * b.x));
}

template<int DIR>
__device__ __forceinline__ void dft4(float2& a, float2& b, float2& c, float2& d) {
    float2 t0 = make_float2(a.x + c.x, a.y + c.y);
    float2 t1 = make_float2(a.x - c.x, a.y - c.y);
    float2 t2 = make_float2(b.x + d.x, b.y + d.y);
    float2 t3 = make_float2(b.x - d.x, b.y - d.y);
    a = make_float2(t0.x + t2.x, t0.y + t2.y);
    c = make_float2(t0.x - t2.x, t0.y - t2.y);
    if (DIR < 0) {
        b = make_float2(t1.x + t3.y, t1.y - t3.x);
        d = make_float2(t1.x - t3.y, t1.y + t3.x);
    } else {
        b = make_float2(t1.x - t3.y, t1.y + t3.x);
        d = make_float2(t1.x + t3.y, t1.y - t3.x);
    }
}

template<int DIR>
__device__ __forceinline__ float2 twc(float2 a, float c, float s) {
    const float si = (DIR < 0) ? -s : s;
    return make_float2(a.x * c - a.y * si, a.x * si + a.y * c);
}

// second layer of DFT16 (twiddles + row dft4s); shared between full/halfzero
template<int DIR>
__device__ __forceinline__ void dft16_layer2(float2 v[16]) {
    const float C1 = 0.9238795325112867f, S1 = 0.3826834323650898f;
    const float R2 = 0.7071067811865476f;
    v[5]  = twc<DIR>(v[5],  C1,  S1);
    v[9]  = twc<DIR>(v[9],  R2,  R2);
    v[13] = twc<DIR>(v[13], S1,  C1);
    v[6]  = twc<DIR>(v[6],  R2,  R2);
    v[10] = (DIR < 0) ? make_float2(v[10].y, -v[10].x)
                      : make_float2(-v[10].y, v[10].x);
    v[14] = twc<DIR>(v[14], -R2,  R2);
    v[7]  = twc<DIR>(v[7],   S1,  C1);
    v[11] = twc<DIR>(v[11], -R2,  R2);
    v[15] = twc<DIR>(v[15], -C1, -S1);
    dft4<DIR>(v[0],  v[1],  v[2],  v[3]);
    dft4<DIR>(v[4],  v[5],  v[6],  v[7]);
    dft4<DIR>(v[8],  v[9],  v[10], v[11]);
    dft4<DIR>(v[12], v[13], v[14], v[15]);
}

// Full DFT16. Output slot s = 4*(r&3)+(r>>2) holds spectral index r.
template<int DIR>
__device__ __forceinline__ void dft16(float2 v[16]) {
    dft4<DIR>(v[0], v[4], v[8],  v[12]);
    dft4<DIR>(v[1], v[5], v[9],  v[13]);
    dft4<DIR>(v[2], v[6], v[10], v[14]);
    dft4<DIR>(v[3], v[7], v[11], v[15]);
    dft16_layer2<DIR>(v);
}

// Forward DFT16 with inputs v[8..15] == 0 (zero-padded upper half).
__device__ __forceinline__ void dft16_fwd_hz(float2 v[16]) {
    #pragma unroll
    for (int k = 0; k < 4; k++) {
        float2 a = v[k], b = v[k + 4];
        v[k]      = make_float2(a.x + b.x, a.y + b.y);       // a + b
        v[k + 4]  = make_float2(a.x + b.y, a.y - b.x);       // a - i b
        v[k + 8]  = make_float2(a.x - b.x, a.y - b.y);       // a - b
        v[k + 12] = make_float2(a.x - b.y, a.y + b.x);       // a + i b
    }
    dft16_layer2<-1>(v);
}

// Generic mid radix-16 smem pass (used for M=1024 and M=64)
template<int DIR, int M>
__device__ __forceinline__ void radix16_stage(float2* s, int tid) {
    constexpr int Ms = M >> 4;
    #pragma unroll
    for (int it = 0; it < (NFFT / 16) / NTHREADS; it++) {
        int g = tid + it * NTHREADS;
        int blk = (g / Ms) * M;
        int j   = g % Ms;
        int base = blk + j;
        float sv, cv;
        sincospif(2.0f * (float)j / (float)M, &sv, &cv);
        float2 w1 = make_float2(cv, (DIR < 0) ? -sv : sv);
        float2 v[16];
        if (DIR < 0) {
            #pragma unroll
            for (int m = 0; m < 16; m++) v[m] = s[PHYS(base + m * Ms)];
            dft16<DIR>(v);
            s[PHYS(base)] = v[0];
            float2 wr = w1;
            #pragma unroll
            for (int r = 1; r < 16; r++) {
                int sl = ((r & 3) << 2) | (r >> 2);
                s[PHYS(base + r * Ms)] = cmulf(v[sl], wr);
                wr = cmulf(wr, w1);
            }
        } else {
            v[0] = s[PHYS(base)];
            float2 wr = w1;
            #pragma unroll
            for (int r = 1; r < 16; r++) {
                v[r] = cmulf(s[PHYS(base + r * Ms)], wr);
                wr = cmulf(wr, w1);
            }
            dft16<DIR>(v);
            #pragma unroll
            for (int m = 0; m < 16; m++) {
                int sl = ((m & 3) << 2) | (m >> 2);
                s[PHYS(base + m * Ms)] = v[sl];
            }
        }
    }
    __syncthreads();
}

// Forward stage 1 (M=NFFT): load v[0..7] straight from global (upper half of
// the padded signal is zero), half-zero DFT16, post-twiddle, store to smem.
__device__ __forceinline__ void fwd_stage1_global(const float2* __restrict__ src,
                                                  float2* s, int tid) {
    #pragma unroll
    for (int it = 0; it < (NFFT / 16) / NTHREADS; it++) {
        int j = tid + it * NTHREADS;             // 0..1023
        float2 v[16];
        #pragma unroll
        for (int m = 0; m < 8; m++) v[m] = src[j + m * (NFFT / 16)];
        dft16_fwd_hz(v);
        float sv, cv;
        sincospif(2.0f * (float)j / (float)NFFT, &sv, &cv);
        float2 w1 = make_float2(cv, -sv);
        s[PHYS(j)] = v[0];
        float2 wr = w1;
        #pragma unroll
        for (int r = 1; r < 16; r++) {
            int sl = ((r & 3) << 2) | (r >> 2);
            s[PHYS(j + r * (NFFT / 16))] = cmulf(v[sl], wr);
            wr = cmulf(wr, w1);
        }
    }
    __syncthreads();
}

// Same for real input rows (h): v[m] = (src[j+m*1024], 0)
__device__ __forceinline__ void fwd_stage1_global_real(const float* __restrict__ src,
                                                       float2* s, int tid) {
    #pragma unroll
    for (int it = 0; it < (NFFT / 16) / NTHREADS; it++) {
        int j = tid + it * NTHREADS;
        float2 v[16];
        #pragma unroll
        for (int m = 0; m < 8; m++) v[m] = make_float2(src[j + m * (NFFT / 16)], 0.f);
        dft16_fwd_hz(v);
        float sv, cv;
        sincospif(2.0f * (float)j / (float)NFFT, &sv, &cv);
        float2 w1 = make_float2(cv, -sv);
        s[PHYS(j)] = v[0];
        float2 wr = w1;
        #pragma unroll
        for (int r = 1; r < 16; r++) {
            int sl = ((r & 3) << 2) | (r >> 2);
            s[PHYS(j + r * (NFFT / 16))] = cmulf(v[sl], wr);
            wr = cmulf(wr, w1);
        }
    }
    __syncthreads();
}

// Fused: forward radix-4 (M=4, unit twiddle) -> ×H -> inverse radix-4,
// entirely in registers; one smem read + one smem write pass.
__device__ __forceinline__ void fused_mul(float2* s, const float2* __restrict__ Hd, int tid) {
    #pragma unroll
    for (int it = 0; it < (NFFT / 4) / NTHREADS; it++) {
        int base = (tid + it * NTHREADS) * 4;
        float2 a = s[PHYS(base + 0)], b = s[PHYS(base + 1)];
        float2 c = s[PHYS(base + 2)], d = s[PHYS(base + 3)];
        dft4<-1>(a, b, c, d);
        float4 h01 = ((const float4*)Hd)[(base >> 1) + 0];
        float4 h23 = ((const float4*)Hd)[(base >> 1) + 1];
        a = cmulf(a, make_float2(h01.x, h01.y));
        b = cmulf(b, make_float2(h01.z, h01.w));
        c = cmulf(c, make_float2(h23.x, h23.y));
        d = cmulf(d, make_float2(h23.z, h23.w));
        dft4<1>(a, b, c, d);
        s[PHYS(base + 0)] = a; s[PHYS(base + 1)] = b;
        s[PHYS(base + 2)] = c; s[PHYS(base + 3)] = d;
    }
    __syncthreads();
}

// Inverse stage (M=NFFT): pre-twiddle, inverse DFT16, write the window
// [START, START+LSEQ) directly to global (coalesced across j).
__device__ __forceinline__ void inv_stage_last_global(float2* s, float2* __restrict__ dst,
                                                      int tid) {
    #pragma unroll
    for (int it = 0; it < (NFFT / 16) / NTHREADS; it++) {
        int j = tid + it * NTHREADS;
        float sv, cv;
        sincospif(2.0f * (float)j / (float)NFFT, &sv, &cv);
        float2 w1 = make_float2(cv, sv);
        float2 v[16];
        v[0] = s[PHYS(j)];
        float2 wr = w1;
        #pragma unroll
        for (int r = 1; r < 16; r++) {
            v[r] = cmulf(s[PHYS(j + r * (NFFT / 16))], wr);
            wr = cmulf(wr, w1);
        }
        dft16<1>(v);
        #pragma unroll
        for (int m = 0; m < 16; m++) {
            int sl = ((m & 3) << 2) | (m >> 2);
            int l = j + m * (NFFT / 16) - START;
            if ((unsigned)l < (unsigned)LSEQ) dst[l] = v[sl];
        }
    }
}

// ---------------------------------------------------------------------------
// Kernel 1: per-batch float2 transpose.  u viewed as (B, L, 128) float2.
// ---------------------------------------------------------------------------
__global__ void __launch_bounds__(256) k_pack(const float* __restrict__ u) {
    __shared__ float2 tile[32][33];
    const int b  = blockIdx.z;
    const int c0 = blockIdx.y * 32;
    const int l0 = blockIdx.x * 32;
    const int tx = threadIdx.x, ty = threadIdx.y;
    const float2* __restrict__ u2 = (const float2*)u;
    #pragma unroll
    for (int i = 0; i < 4; i++) {
        int l = l0 + ty + 8 * i;
        tile[tx][ty + 8 * i] = u2[((size_t)b * LSEQ + l) * CPAIR + (c0 + tx)];
    }
    __syncthreads();
    #pragma unroll
    for (int i = 0; i < 4; i++) {
        int c = c0 + ty + 8 * i;
        int l = l0 + tx;
        g_Z[((size_t)b * CPAIR + c) * LSEQ + l] = tile[ty + 8 * i][tx];
    }
}

// ---------------------------------------------------------------------------
// Kernel 2: filter spectra, digit-reversed order, pre-scaled 1/N
// ---------------------------------------------------------------------------
__global__ void __launch_bounds__(NTHREADS, 1) k_hfft(const float* __restrict__ h) {
    extern __shared__ float2 s[];
    const int d = blockIdx.x, tid = threadIdx.x;
    fwd_stage1_global_real(h + (size_t)d * KLEN, s, tid);
    radix16_stage<-1, 1024>(s, tid);
    radix16_stage<-1, 64>(s, tid);
    const float inv = 1.0f / (float)NFFT;
    float2* __restrict__ Hd = g_H + (size_t)d * NFFT;
    #pragma unroll
    for (int it = 0; it < (NFFT / 4) / NTHREADS; it++) {
        int base = (tid + it * NTHREADS) * 4;
        float2 a = s[PHYS(base + 0)], b = s[PHYS(base + 1)];
        float2 c = s[PHYS(base + 2)], e = s[PHYS(base + 3)];
        dft4<-1>(a, b, c, e);
        Hd[base + 0] = make_float2(a.x * inv, a.y * inv);
        Hd[base + 1] = make_float2(b.x * inv, b.y * inv);
        Hd[base + 2] = make_float2(c.x * inv, c.y * inv);
        Hd[base + 3] = make_float2(e.x * inv, e.y * inv);
    }
}

// ---------------------------------------------------------------------------
// Kernel 3: per packed row: FFT -> .*H -> IFFT -> window -> g_W
// ---------------------------------------------------------------------------
__global__ void __launch_bounds__(NTHREADS, 1) k_conv() {
    extern __shared__ float2 s[];
    const int row = blockIdx.x;
    const int phi = row >> 2;
    const int tid = threadIdx.x;
    fwd_stage1_global(g_Z + (size_t)row * LSEQ, s, tid);
    radix16_stage<-1, 1024>(s, tid);
    radix16_stage<-1, 64>(s, tid);
    fused_mul(s, g_H + (size_t)phi * NFFT, tid);
    radix16_stage<1, 64>(s, tid);
    radix16_stage<1, 1024>(s, tid);
    inv_stage_last_global(s, g_W + (size_t)row * LSEQ, tid);
}

// ---------------------------------------------------------------------------
// Kernel 4: per-batch float2 transpose back.
// ---------------------------------------------------------------------------
__global__ void __launch_bounds__(256) k_unpack(float* __restrict__ y) {
    __shared__ float2 tile[32][33];
    const int b  = blockIdx.z;
    const int c0 = blockIdx.y * 32;
    const int l0 = blockIdx.x * 32;
    const int tx = threadIdx.x, ty = threadIdx.y;
    float2* __restrict__ y2 = (float2*)y;
    #pragma unroll
    for (int i = 0; i < 4; i++) {
        int c = c0 + ty + 8 * i;
        int l = l0 + tx;
        tile[ty + 8 * i][tx] = g_W[((size_t)b * CPAIR + c) * LSEQ + l];
    }
    __syncthreads();
    #pragma unroll
    for (int i = 0; i < 4; i++) {
        int l = l0 + ty + 8 * i;
        y2[((size_t)b * LSEQ + l) * CPAIR + (c0 + tx)] = tile[tx][ty + 8 * i];
    }
}

// ---------------------------------------------------------------------------
extern "C" void kernel_launch(void* const* d_in, const int* in_sizes, int n_in,
                              void* d_out, int out_size) {
    (void)in_sizes; (void)n_in; (void)out_size;
    const float* u = (const float*)d_in[0];
    const float* h = (const float*)d_in[1];
    float* y = (float*)d_out;

    cudaFuncSetAttribute(k_hfft, cudaFuncAttributeMaxDynamicSharedMemorySize, SMEM_BYTES);
    cudaFuncSetAttribute(k_conv, cudaFuncAttributeMaxDynamicSharedMemorySize, SMEM_BYTES);

    dim3 tb(32, 8);
    dim3 tg(LSEQ / 32, CPAIR / 32, BATCH);

    k_pack<<<tg, tb>>>(u);
    k_hfft<<<DDIM, NTHREADS, SMEM_BYTES>>>(h);
    k_conv<<<NROWS, NTHREADS, SMEM_BYTES>>>();
    k_unpack<<<tg, tb>>>(y);
}